// round 12
// baseline (speedup 1.0000x reference)
#include <cuda_runtime.h>
#include <stdint.h>

// Problem constants (fixed by the reference)
#define NXD   432
#define NYD   496
#define BD    4
#define CD    64
#define PLANE (NXD * NYD)        // 214272 = 837 * 256 (exact)
#define NBINS 3
#define NPIL  64000              // p+1 <= 64000 -> fits uint16
#define NBB   (NBINS * BD)       // 12 (bin,b) canvases

// Pillar-index canvas. Encoding: 0 = empty, p+1 = pillar index p.
// Zero-initialized at module load; the gather kernel restores every entry
// to 0 after reading it, so the canvas is all-"empty" at the start of every
// kernel_launch call. No init kernel needed.
__device__ unsigned short g_idx[NBB * PLANE];   // 5.1 MB, L2-resident

// ---------------------------------------------------------------------------
// Kernel 1: scatter pillar indices (p+1) into the canvas.
// coords row layout: [b, z, y, x]; local = z + y*NX + x  (nz == 1)
// ---------------------------------------------------------------------------
__global__ void scatter_idx_kernel(const int* __restrict__ c0,
                                   const int* __restrict__ c1,
                                   const int* __restrict__ c2) {
    int t = blockIdx.x * blockDim.x + threadIdx.x;
    if (t >= NBINS * NPIL) return;
    int bin = t / NPIL;
    int p   = t - bin * NPIL;
    const int* cbase = (bin == 0) ? c0 : (bin == 1) ? c1 : c2;
    int4 cr = reinterpret_cast<const int4*>(cbase)[p];   // [b, z, y, x]
    int local = cr.y + cr.z * NXD + cr.w;
    g_idx[(bin * BD + cr.x) * PLANE + local] = (unsigned short)(p + 1);
}

// ---------------------------------------------------------------------------
// Kernel 2: branch-free gather. Identical store/load pattern to the 119.5us
// winner; ONLY change: 8 chunks of 8 channels (2 float4 live instead of 4)
// to cut register pressure (~40 -> ~32 regs) and lift occupancy to 64 warps.
// One thread per BEV position, all 64 channels:
//  - index load: coalesced u16 (+ self-clearing store back to 0)
//  - pillar row: 16 x LDG.128 via clamped pointer (occupied rows read once
//    chip-wide; empty lanes broadcast row 0 -> L1 hit)
//  - stores: 64 unconditional warp-coalesced plain STG.32 (128B/warp/instr)
// ---------------------------------------------------------------------------
__global__ void __launch_bounds__(256, 8)
gather_kernel(const float* __restrict__ p0,
              const float* __restrict__ p1,
              const float* __restrict__ p2,
              float* __restrict__ out) {
    int pos = blockIdx.x * 256 + threadIdx.x;  // 0..PLANE-1 (exact cover)
    int bb  = blockIdx.y;                      // 0..11 = bin*4 + b
    int bin = bb >> 2;
    const float* pil = (bin == 0) ? p0 : (bin == 1) ? p1 : p2;

    unsigned short* ip = g_idx + (size_t)bb * PLANE + pos;
    unsigned int idx = *ip;
    *ip = 0;                                   // restore empty state
    bool occ = idx != 0u;

    const float4* row =
        reinterpret_cast<const float4*>(pil) + (size_t)(occ ? idx - 1u : 0u) * (CD / 4);
    float* o = out + (size_t)bb * CD * PLANE + pos;

#pragma unroll
    for (int ch = 0; ch < 8; ch++) {           // 8 chunks of 8 channels
        float4 r0 = __ldg(row + ch * 2 + 0);
        float4 r1 = __ldg(row + ch * 2 + 1);
        int c = ch * 8;
        o[(size_t)(c + 0) * PLANE] = occ ? r0.x : 0.f;
        o[(size_t)(c + 1) * PLANE] = occ ? r0.y : 0.f;
        o[(size_t)(c + 2) * PLANE] = occ ? r0.z : 0.f;
        o[(size_t)(c + 3) * PLANE] = occ ? r0.w : 0.f;
        o[(size_t)(c + 4) * PLANE] = occ ? r1.x : 0.f;
        o[(size_t)(c + 5) * PLANE] = occ ? r1.y : 0.f;
        o[(size_t)(c + 6) * PLANE] = occ ? r1.z : 0.f;
        o[(size_t)(c + 7) * PLANE] = occ ? r1.w : 0.f;
    }
}

// ---------------------------------------------------------------------------
// Launch. Input order (metadata): pf0, vc0, pf1, vc1, pf2, vc2.
// Output: 3 canvases [4,64,496,432] f32 concatenated.
// ---------------------------------------------------------------------------
extern "C" void kernel_launch(void* const* d_in, const int* in_sizes, int n_in,
                              void* d_out, int out_size) {
    const float* pf0 = (const float*)d_in[0];
    const int*   vc0 = (const int*)  d_in[1];
    const float* pf1 = (const float*)d_in[2];
    const int*   vc1 = (const int*)  d_in[3];
    const float* pf2 = (const float*)d_in[4];
    const int*   vc2 = (const int*)  d_in[5];
    float* out = (float*)d_out;

    // 1) scatter pillar indices into the (all-empty) canvas
    {
        int n = NBINS * NPIL;
        scatter_idx_kernel<<<(n + 255) / 256, 256>>>(vc0, vc1, vc2);
    }
    // 2) branch-free gather -> dense output; self-clears the canvas
    {
        dim3 blocks(PLANE / 256, NBB);   // (837, 12), exact cover
        gather_kernel<<<blocks, 256>>>(pf0, pf1, pf2, out);
    }
}